// round 1
// baseline (speedup 1.0000x reference)
#include <cuda_runtime.h>
#include <math.h>

#define B_  8192
#define IN_ 1024
#define H_  2048
#define NH_ 4
#define HD_ 512
#define EPS_ 1e-5f

// Scratch (allocation-free rule: __device__ globals).
// buf0: x_proj -> attn_gelu ; buf1: q -> gate ; buf2: attn
__device__ float g_buf0[(size_t)B_ * H_];
__device__ float g_buf1[(size_t)B_ * H_];
__device__ float g_buf2[(size_t)B_ * H_];

// ---------------------------------------------------------------------------
// SGEMM (NT): C[M,N] = act( A[M,K] @ Bm[N,K]^T + bias[N] )
// A is logically the row-wise concat of A0 (first Ks cols) and A1 (rest).
// All dims multiples of tile sizes (M%128==0, N%128==0, K%16==0, Ks%16==0).
// ACT: 0 = identity, 1 = exact GELU, 2 = sigmoid.
// ---------------------------------------------------------------------------
template<int ACT>
__global__ void __launch_bounds__(256)
sgemm_nt(const float* __restrict__ A0, const float* __restrict__ A1, int Ks,
         const float* __restrict__ Bm, const float* __restrict__ bias,
         float* __restrict__ C, int M, int N, int K)
{
    const int BM = 128, BN = 128, BK = 16;
    __shared__ __align__(16) float As[BK][BM + 4];
    __shared__ __align__(16) float Bs[BK][BN + 4];

    const int tid  = threadIdx.x;
    const int bm   = blockIdx.y * BM;
    const int bn   = blockIdx.x * BN;
    const int lrow = tid >> 2;            // 0..63 (two rows: lrow, lrow+64)
    const int lcol = (tid & 3) << 2;      // 0,4,8,12
    const int ty   = tid >> 4;            // 0..15
    const int tx   = tid & 15;            // 0..15

    float acc[8][8];
#pragma unroll
    for (int i = 0; i < 8; i++)
#pragma unroll
        for (int j = 0; j < 8; j++) acc[i][j] = 0.0f;

    for (int k0 = 0; k0 < K; k0 += BK) {
        // ---- load A tile (select source half; Ks is a multiple of BK) ----
        const float* Ap;
        int lda;
        if (k0 < Ks) { Ap = A0; lda = Ks;      Ap += (size_t)(bm + lrow) * lda + k0 + lcol; }
        else         { Ap = A1; lda = K - Ks;  Ap += (size_t)(bm + lrow) * lda + (k0 - Ks) + lcol; }
#pragma unroll
        for (int r = 0; r < 2; r++) {
            float4 v = *(const float4*)(Ap + (size_t)r * 64 * lda);
            int row = lrow + r * 64;
            As[lcol + 0][row] = v.x;
            As[lcol + 1][row] = v.y;
            As[lcol + 2][row] = v.z;
            As[lcol + 3][row] = v.w;
        }
        // ---- load B tile ----
        const float* Bp = Bm + (size_t)(bn + lrow) * K + k0 + lcol;
#pragma unroll
        for (int r = 0; r < 2; r++) {
            float4 v = *(const float4*)(Bp + (size_t)r * 64 * K);
            int row = lrow + r * 64;
            Bs[lcol + 0][row] = v.x;
            Bs[lcol + 1][row] = v.y;
            Bs[lcol + 2][row] = v.z;
            Bs[lcol + 3][row] = v.w;
        }
        __syncthreads();

#pragma unroll
        for (int k = 0; k < BK; k++) {
            float4 a0 = *(const float4*)&As[k][ty * 8];
            float4 a1 = *(const float4*)&As[k][ty * 8 + 4];
            float4 b0 = *(const float4*)&Bs[k][tx * 8];
            float4 b1 = *(const float4*)&Bs[k][tx * 8 + 4];
            float ra[8] = {a0.x, a0.y, a0.z, a0.w, a1.x, a1.y, a1.z, a1.w};
            float rb[8] = {b0.x, b0.y, b0.z, b0.w, b1.x, b1.y, b1.z, b1.w};
#pragma unroll
            for (int i = 0; i < 8; i++)
#pragma unroll
                for (int j = 0; j < 8; j++)
                    acc[i][j] = fmaf(ra[i], rb[j], acc[i][j]);
        }
        __syncthreads();
    }

    // ---- epilogue: bias + activation ----
    float bb[8];
#pragma unroll
    for (int j = 0; j < 8; j++) bb[j] = bias[bn + tx * 8 + j];

#pragma unroll
    for (int i = 0; i < 8; i++) {
        float* Crow = C + (size_t)(bm + ty * 8 + i) * N + bn + tx * 8;
        float v[8];
#pragma unroll
        for (int j = 0; j < 8; j++) {
            float x = acc[i][j] + bb[j];
            if (ACT == 1) x = 0.5f * x * (1.0f + erff(x * 0.70710678118654752f));
            else if (ACT == 2) x = 1.0f / (1.0f + expf(-x));
            v[j] = x;
        }
        *(float4*)(Crow)     = make_float4(v[0], v[1], v[2], v[3]);
        *(float4*)(Crow + 4) = make_float4(v[4], v[5], v[6], v[7]);
    }
}

// ---------------------------------------------------------------------------
// Attention over 4 keys per (batch, head): one warp per (b, head).
// keys: k0=h, k1=xp, k2=h+xp, k3=h*xp ; s2 = s0+s1 exactly.
// attn[d] = (w0+w2)*h[d] + (w1+w2)*xp[d] + w3*h[d]*xp[d]
// ---------------------------------------------------------------------------
__global__ void __launch_bounds__(256)
attn_kernel(const float* __restrict__ h_prev, const float* __restrict__ xproj,
            const float* __restrict__ q, float* __restrict__ attn)
{
    const int gw   = (blockIdx.x * 256 + threadIdx.x) >> 5;   // global warp id
    const int lane = threadIdx.x & 31;
    if (gw >= B_ * NH_) return;
    const size_t base = (size_t)(gw / NH_) * H_ + (size_t)(gw % NH_) * HD_;

    const float4* qp = (const float4*)(q + base);
    const float4* hp = (const float4*)(h_prev + base);
    const float4* xp = (const float4*)(xproj + base);

    float s0 = 0.f, s1 = 0.f, s3 = 0.f;
    float4 hv[4], xv[4];
#pragma unroll
    for (int i = 0; i < 4; i++) {
        float4 q4 = qp[i * 32 + lane];
        float4 h4 = hp[i * 32 + lane];
        float4 x4 = xp[i * 32 + lane];
        hv[i] = h4; xv[i] = x4;
        s0 += q4.x * h4.x + q4.y * h4.y + q4.z * h4.z + q4.w * h4.w;
        s1 += q4.x * x4.x + q4.y * x4.y + q4.z * x4.z + q4.w * x4.w;
        s3 += q4.x * h4.x * x4.x + q4.y * h4.y * x4.y +
              q4.z * h4.z * x4.z + q4.w * h4.w * x4.w;
    }
#pragma unroll
    for (int off = 16; off > 0; off >>= 1) {
        s0 += __shfl_xor_sync(0xffffffffu, s0, off);
        s1 += __shfl_xor_sync(0xffffffffu, s1, off);
        s3 += __shfl_xor_sync(0xffffffffu, s3, off);
    }
    const float inv = rsqrtf((float)HD_);
    float sc0 = s0 * inv, sc1 = s1 * inv, sc2 = (s0 + s1) * inv, sc3 = s3 * inv;
    float m  = fmaxf(fmaxf(sc0, sc1), fmaxf(sc2, sc3));
    float e0 = expf(sc0 - m), e1 = expf(sc1 - m), e2 = expf(sc2 - m), e3 = expf(sc3 - m);
    float rs = 1.0f / (e0 + e1 + e2 + e3);
    float w0 = e0 * rs, w1 = e1 * rs, w2 = e2 * rs, w3 = e3 * rs;
    float ch = w0 + w2, cx = w1 + w2;

    float4* op = (float4*)(attn + base);
#pragma unroll
    for (int i = 0; i < 4; i++) {
        float4 h4 = hv[i], x4 = xv[i], o4;
        o4.x = ch * h4.x + cx * x4.x + w3 * h4.x * x4.x;
        o4.y = ch * h4.y + cx * x4.y + w3 * h4.y * x4.y;
        o4.z = ch * h4.z + cx * x4.z + w3 * h4.z * x4.z;
        o4.w = ch * h4.w + cx * x4.w + w3 * h4.w * x4.w;
        op[i * 32 + lane] = o4;
    }
}

// ---------------------------------------------------------------------------
// Final: y = attn_gelu + h_prev; h_cand = LN(y)*gamma+beta;
//        out = gate*h_cand + (1-gate)*h_prev.   One block (256 thr) per row.
// ---------------------------------------------------------------------------
__global__ void __launch_bounds__(256)
ln_gate_kernel(const float* __restrict__ attn_g, const float* __restrict__ h_prev,
               const float* __restrict__ gate, const float* __restrict__ gamma,
               const float* __restrict__ beta, float* __restrict__ out)
{
    const int b   = blockIdx.x;
    const int tid = threadIdx.x;
    const size_t rb = (size_t)b * H_;

    float4 y[2], h4[2];
    float sum = 0.f, sq = 0.f;
#pragma unroll
    for (int c = 0; c < 2; c++) {
        int d = c * 1024 + tid * 4;
        float4 a  = *(const float4*)(attn_g + rb + d);
        float4 hh = *(const float4*)(h_prev + rb + d);
        float4 yy = make_float4(a.x + hh.x, a.y + hh.y, a.z + hh.z, a.w + hh.w);
        y[c] = yy; h4[c] = hh;
        sum += yy.x + yy.y + yy.z + yy.w;
        sq  += yy.x * yy.x + yy.y * yy.y + yy.z * yy.z + yy.w * yy.w;
    }
#pragma unroll
    for (int off = 16; off > 0; off >>= 1) {
        sum += __shfl_xor_sync(0xffffffffu, sum, off);
        sq  += __shfl_xor_sync(0xffffffffu, sq,  off);
    }
    __shared__ float s_sum[8], s_sq[8];
    __shared__ float s_mu, s_rstd;
    if ((tid & 31) == 0) { s_sum[tid >> 5] = sum; s_sq[tid >> 5] = sq; }
    __syncthreads();
    if (tid == 0) {
        float S = 0.f, Q = 0.f;
#pragma unroll
        for (int i = 0; i < 8; i++) { S += s_sum[i]; Q += s_sq[i]; }
        float mu  = S / (float)H_;
        float var = Q / (float)H_ - mu * mu;
        s_mu = mu;
        s_rstd = rsqrtf(var + EPS_);
    }
    __syncthreads();
    const float mu = s_mu, rstd = s_rstd;

#pragma unroll
    for (int c = 0; c < 2; c++) {
        int d = c * 1024 + tid * 4;
        float4 g4 = *(const float4*)(gate  + rb + d);
        float4 gm = *(const float4*)(gamma + d);
        float4 bt = *(const float4*)(beta  + d);
        float4 yy = y[c], hh = h4[c], o;
        float c0 = (yy.x - mu) * rstd * gm.x + bt.x;
        float c1 = (yy.y - mu) * rstd * gm.y + bt.y;
        float c2 = (yy.z - mu) * rstd * gm.z + bt.z;
        float c3 = (yy.w - mu) * rstd * gm.w + bt.w;
        o.x = g4.x * c0 + (1.0f - g4.x) * hh.x;
        o.y = g4.y * c1 + (1.0f - g4.y) * hh.y;
        o.z = g4.z * c2 + (1.0f - g4.z) * hh.z;
        o.w = g4.w * c3 + (1.0f - g4.w) * hh.w;
        *(float4*)(out + rb + d) = o;
    }
}

// ---------------------------------------------------------------------------
extern "C" void kernel_launch(void* const* d_in, const int* in_sizes, int n_in,
                              void* d_out, int out_size)
{
    const float* h_prev = (const float*)d_in[0];
    const float* x      = (const float*)d_in[1];
    const float* W_proj = (const float*)d_in[2];
    const float* b_proj = (const float*)d_in[3];
    const float* W_q    = (const float*)d_in[4];
    const float* b_q    = (const float*)d_in[5];
    const float* W_o    = (const float*)d_in[6];
    const float* b_o    = (const float*)d_in[7];
    const float* W_g    = (const float*)d_in[8];
    const float* b_g    = (const float*)d_in[9];
    const float* gamma  = (const float*)d_in[10];
    const float* beta   = (const float*)d_in[11];
    float* out = (float*)d_out;

    float *buf0, *buf1, *buf2;
    cudaGetSymbolAddress((void**)&buf0, g_buf0);
    cudaGetSymbolAddress((void**)&buf1, g_buf1);
    cudaGetSymbolAddress((void**)&buf2, g_buf2);

    dim3 grid(H_ / 128, B_ / 128);

    // 1) x_proj = x @ W_proj^T + b_proj            -> buf0
    sgemm_nt<0><<<grid, 256>>>(x, x, IN_, W_proj, b_proj, buf0, B_, H_, IN_);
    // 2) q = h_prev @ W_q^T + b_q                  -> buf1
    sgemm_nt<0><<<grid, 256>>>(h_prev, h_prev, H_, W_q, b_q, buf1, B_, H_, H_);
    // 3) 4-key attention                           -> buf2
    attn_kernel<<<(B_ * NH_) / 8, 256>>>(h_prev, buf0, buf1, buf2);
    // 4) attn_gelu = gelu(attn @ W_o^T + b_o)      -> buf0
    sgemm_nt<1><<<grid, 256>>>(buf2, buf2, H_, W_o, b_o, buf0, B_, H_, H_);
    // 5) gate = sigmoid([h_prev, attn_gelu] @ W_g^T + b_g) -> buf1
    sgemm_nt<2><<<grid, 256>>>(h_prev, buf0, H_, W_g, b_g, buf1, B_, H_, 2 * H_);
    // 6) layernorm + gated mix                     -> out
    ln_gate_kernel<<<B_, 256>>>(buf0, h_prev, buf1, gamma, beta, out);
}

// round 3
// speedup vs baseline: 2.0055x; 2.0055x over previous
#include <cuda_runtime.h>
#include <cuda_bf16.h>
#include <math.h>
#include <stdint.h>

#define B_  8192
#define IN_ 1024
#define H_  2048
#define NH_ 4
#define HD_ 512
#define EPS_ 1e-5f

// ---------------------------------------------------------------------------
// Device scratch (allocation-free rule)
// ---------------------------------------------------------------------------
__device__ __align__(128) float g_buf0[(size_t)B_ * H_];   // x_proj (fp32)
__device__ __align__(128) float g_buf1[(size_t)B_ * H_];   // q -> gate (fp32)
__device__ __align__(128) float g_buf2[(size_t)B_ * H_];   // attn_gelu (fp32)

__device__ __align__(128) __nv_bfloat16 g_xs_hi[(size_t)B_ * IN_];
__device__ __align__(128) __nv_bfloat16 g_xs_lo[(size_t)B_ * IN_];
__device__ __align__(128) __nv_bfloat16 g_hs_hi[(size_t)B_ * H_];
__device__ __align__(128) __nv_bfloat16 g_hs_lo[(size_t)B_ * H_];
__device__ __align__(128) __nv_bfloat16 g_at_hi[(size_t)B_ * H_];
__device__ __align__(128) __nv_bfloat16 g_at_lo[(size_t)B_ * H_];
__device__ __align__(128) __nv_bfloat16 g_ag_hi[(size_t)B_ * H_];
__device__ __align__(128) __nv_bfloat16 g_ag_lo[(size_t)B_ * H_];

__device__ __align__(128) __nv_bfloat16 g_wp_hi[(size_t)H_ * IN_];
__device__ __align__(128) __nv_bfloat16 g_wp_lo[(size_t)H_ * IN_];
__device__ __align__(128) __nv_bfloat16 g_wq_hi[(size_t)H_ * H_];
__device__ __align__(128) __nv_bfloat16 g_wq_lo[(size_t)H_ * H_];
__device__ __align__(128) __nv_bfloat16 g_wo_hi[(size_t)H_ * H_];
__device__ __align__(128) __nv_bfloat16 g_wo_lo[(size_t)H_ * H_];
__device__ __align__(128) __nv_bfloat16 g_wg_hi[(size_t)H_ * 2 * H_];
__device__ __align__(128) __nv_bfloat16 g_wg_lo[(size_t)H_ * 2 * H_];

// ---------------------------------------------------------------------------
// PTX helpers (base-target-safe: cp.async / ldmatrix / mma.sync only)
// ---------------------------------------------------------------------------
__device__ __forceinline__ uint32_t smem_u32(const void* p) {
    uint32_t a;
    asm("{ .reg .u64 t; cvta.to.shared.u64 t, %1; cvt.u32.u64 %0, t; }" : "=r"(a) : "l"(p));
    return a;
}

#define CP_ASYNC16(sa, ga) \
    asm volatile("cp.async.cg.shared.global [%0], [%1], 16;\n" :: "r"(sa), "l"(ga))
#define CP_COMMIT()  asm volatile("cp.async.commit_group;\n" ::: "memory")
#define CP_WAIT0()   asm volatile("cp.async.wait_group 0;\n" ::: "memory")
#define CP_WAIT1()   asm volatile("cp.async.wait_group 1;\n" ::: "memory")

#define LDSM_X4(r0, r1, r2, r3, addr) \
    asm volatile("ldmatrix.sync.aligned.m8n8.x4.shared.b16 {%0,%1,%2,%3}, [%4];" \
        : "=r"(r0), "=r"(r1), "=r"(r2), "=r"(r3) : "r"(addr))

#define MMA_BF16(c0, c1, c2, c3, a0, a1, a2, a3, b0, b1) \
    asm volatile("mma.sync.aligned.m16n8k16.row.col.f32.bf16.bf16.f32 " \
        "{%0,%1,%2,%3}, {%4,%5,%6,%7}, {%8,%9}, {%0,%1,%2,%3};" \
        : "+f"(c0), "+f"(c1), "+f"(c2), "+f"(c3) \
        : "r"(a0), "r"(a1), "r"(a2), "r"(a3), "r"(b0), "r"(b1))

// ---------------------------------------------------------------------------
// SMEM geometry: per stage, four 128x32 bf16 tiles (Ah, Al, Bh, Bl),
// each stored with padded stride 40 elems (80B rows -> conflict-free ldmatrix).
// ---------------------------------------------------------------------------
#define SSTR 40
#define TILE_ELEMS (128 * SSTR)            // 5120
#define STAGE_ELEMS (4 * TILE_ELEMS)       // 20480
#define OFF_AH 0
#define OFF_AL TILE_ELEMS
#define OFF_BH (2 * TILE_ELEMS)
#define OFF_BL (3 * TILE_ELEMS)
#define SMEM_BYTES (2 * STAGE_ELEMS * 2)   // 81920

// ---------------------------------------------------------------------------
// Split-bf16 GEMM on HMMA:  C[M,N] = act( A @ B^T + bias )
// A logically = concat(A0[:, :Ks], A1[:, Ks:]) row-major (hi/lo pairs).
// CTA tile 128x128, warp tile 64x32, K-chunk 32, 2-stage cp.async pipeline.
// ACT: 0 none, 1 exact gelu, 2 sigmoid. SPLIT_OUT also writes bf16 hi/lo.
// ---------------------------------------------------------------------------
template<int ACT, bool SPLIT_OUT>
__global__ void __launch_bounds__(256, 1)
gemm_mma(const __nv_bfloat16* __restrict__ a0h, const __nv_bfloat16* __restrict__ a0l,
         const __nv_bfloat16* __restrict__ a1h, const __nv_bfloat16* __restrict__ a1l, int Ks,
         const __nv_bfloat16* __restrict__ bhp, const __nv_bfloat16* __restrict__ blp,
         const float* __restrict__ bias, float* __restrict__ C,
         __nv_bfloat16* __restrict__ ohi, __nv_bfloat16* __restrict__ olo,
         int M, int N, int K)
{
    extern __shared__ __align__(128) char smem[];
    const uint32_t sbase = smem_u32(smem);
    const int tid  = threadIdx.x;
    const int warp = tid >> 5;
    const int lane = tid & 31;
    const int bm = blockIdx.y * 128;
    const int bn = blockIdx.x * 128;
    const int wm = (warp >> 2) * 64;       // 0 or 64
    const int wn = (warp & 3) * 32;        // 0..96

    float acc[4][4][4];
#pragma unroll
    for (int i = 0; i < 4; i++)
#pragma unroll
        for (int j = 0; j < 4; j++)
#pragma unroll
            for (int r = 0; r < 4; r++) acc[i][j][r] = 0.0f;

    const int nk = K / 32;

    // ---- stage loader: 2 chunk-pairs per thread for A, 2 for B ----
    auto load_stage = [&](int stage, int k0) {
        const __nv_bfloat16 *ah, *al;
        int lda, kk;
        if (k0 < Ks) { ah = a0h; al = a0l; lda = Ks;     kk = k0; }
        else         { ah = a1h; al = a1l; lda = K - Ks; kk = k0 - Ks; }
        const uint32_t stb = sbase + (uint32_t)stage * STAGE_ELEMS * 2;
#pragma unroll
        for (int r = 0; r < 2; r++) {
            const int c   = tid + r * 256;        // chunk 0..511
            const int row = c >> 2;
            const int seg = c & 3;
            const uint32_t so = stb + (uint32_t)(row * SSTR + seg * 8) * 2;
            const size_t ga = (size_t)(bm + row) * lda + kk + seg * 8;
            CP_ASYNC16(so + OFF_AH * 2, ah + ga);
            CP_ASYNC16(so + OFF_AL * 2, al + ga);
            const size_t gb = (size_t)(bn + row) * K + k0 + seg * 8;
            CP_ASYNC16(so + OFF_BH * 2, bhp + gb);
            CP_ASYNC16(so + OFF_BL * 2, blp + gb);
        }
        CP_COMMIT();
    };

    // ldmatrix lane geometry (same for A and B x4 loads)
    const int lrow = (lane & 7) + ((lane >> 3) & 1) * 8;   // 0..15
    const int lcol = (lane >> 4) * 8;                      // 0 or 8

    load_stage(0, 0);

    for (int kc = 0; kc < nk; kc++) {
        if (kc + 1 < nk) { load_stage((kc + 1) & 1, (kc + 1) * 32); CP_WAIT1(); }
        else             { CP_WAIT0(); }
        __syncthreads();

        const uint32_t stb = sbase + (uint32_t)(kc & 1) * STAGE_ELEMS * 2;
#pragma unroll
        for (int ks = 0; ks < 2; ks++) {
            const int kb = ks * 16 + lcol;
            uint32_t ah[4][4], al[4][4];
#pragma unroll
            for (int i = 0; i < 4; i++) {
                const uint32_t ad = stb + (uint32_t)((wm + i * 16 + lrow) * SSTR + kb) * 2;
                LDSM_X4(ah[i][0], ah[i][1], ah[i][2], ah[i][3], ad + OFF_AH * 2);
                LDSM_X4(al[i][0], al[i][1], al[i][2], al[i][3], ad + OFF_AL * 2);
            }
            uint32_t bh[4][2], bl[4][2];
#pragma unroll
            for (int p = 0; p < 2; p++) {
                const uint32_t bd = stb + (uint32_t)((wn + p * 16 + lrow) * SSTR + kb) * 2;
                uint32_t r0, r1, r2, r3;
                LDSM_X4(r0, r1, r2, r3, bd + OFF_BH * 2);
                bh[2*p][0] = r0; bh[2*p+1][0] = r1; bh[2*p][1] = r2; bh[2*p+1][1] = r3;
                LDSM_X4(r0, r1, r2, r3, bd + OFF_BL * 2);
                bl[2*p][0] = r0; bl[2*p+1][0] = r1; bl[2*p][1] = r2; bl[2*p+1][1] = r3;
            }
#pragma unroll
            for (int i = 0; i < 4; i++) {
#pragma unroll
                for (int j = 0; j < 4; j++) {
                    float* c = acc[i][j];
                    MMA_BF16(c[0], c[1], c[2], c[3],
                             ah[i][0], ah[i][1], ah[i][2], ah[i][3], bh[j][0], bh[j][1]);
                    MMA_BF16(c[0], c[1], c[2], c[3],
                             ah[i][0], ah[i][1], ah[i][2], ah[i][3], bl[j][0], bl[j][1]);
                    MMA_BF16(c[0], c[1], c[2], c[3],
                             al[i][0], al[i][1], al[i][2], al[i][3], bh[j][0], bh[j][1]);
                }
            }
        }
        __syncthreads();
    }

    // ---- epilogue: bias + activation (+ optional bf16 split) ----
    const int tr = lane >> 2;
    const int tc = (lane & 3) * 2;
#pragma unroll
    for (int i = 0; i < 4; i++) {
        const int r0 = bm + wm + i * 16 + tr;
        const int r1 = r0 + 8;
#pragma unroll
        for (int j = 0; j < 4; j++) {
            const int col = bn + wn + j * 8 + tc;
            const float b0 = bias[col], b1 = bias[col + 1];
            float v[4] = {acc[i][j][0] + b0, acc[i][j][1] + b1,
                          acc[i][j][2] + b0, acc[i][j][3] + b1};
#pragma unroll
            for (int r = 0; r < 4; r++) {
                if (ACT == 1)      v[r] = 0.5f * v[r] * (1.0f + erff(v[r] * 0.70710678118654752f));
                else if (ACT == 2) v[r] = 1.0f / (1.0f + expf(-v[r]));
            }
            *(float2*)(C + (size_t)r0 * N + col) = make_float2(v[0], v[1]);
            *(float2*)(C + (size_t)r1 * N + col) = make_float2(v[2], v[3]);
            if (SPLIT_OUT) {
                __nv_bfloat16 h0 = __float2bfloat16(v[0]), h1 = __float2bfloat16(v[1]);
                __nv_bfloat16 h2 = __float2bfloat16(v[2]), h3 = __float2bfloat16(v[3]);
                __nv_bfloat16 l0 = __float2bfloat16(v[0] - __bfloat162float(h0));
                __nv_bfloat16 l1 = __float2bfloat16(v[1] - __bfloat162float(h1));
                __nv_bfloat16 l2 = __float2bfloat16(v[2] - __bfloat162float(h2));
                __nv_bfloat16 l3 = __float2bfloat16(v[3] - __bfloat162float(h3));
                *(__nv_bfloat162*)(ohi + (size_t)r0 * N + col) = __nv_bfloat162{h0, h1};
                *(__nv_bfloat162*)(ohi + (size_t)r1 * N + col) = __nv_bfloat162{h2, h3};
                *(__nv_bfloat162*)(olo + (size_t)r0 * N + col) = __nv_bfloat162{l0, l1};
                *(__nv_bfloat162*)(olo + (size_t)r1 * N + col) = __nv_bfloat162{l2, l3};
            }
        }
    }
}

// ---------------------------------------------------------------------------
// fp32 -> (bf16 hi, bf16 lo) split
// ---------------------------------------------------------------------------
__global__ void __launch_bounds__(256)
split_kernel(const float* __restrict__ in, __nv_bfloat16* __restrict__ hi,
             __nv_bfloat16* __restrict__ lo, int n4)
{
    int i = blockIdx.x * 256 + threadIdx.x;
    if (i >= n4) return;
    float4 v = ((const float4*)in)[i];
    __nv_bfloat16 h0 = __float2bfloat16(v.x), h1 = __float2bfloat16(v.y);
    __nv_bfloat16 h2 = __float2bfloat16(v.z), h3 = __float2bfloat16(v.w);
    __nv_bfloat16 l0 = __float2bfloat16(v.x - __bfloat162float(h0));
    __nv_bfloat16 l1 = __float2bfloat16(v.y - __bfloat162float(h1));
    __nv_bfloat16 l2 = __float2bfloat16(v.z - __bfloat162float(h2));
    __nv_bfloat16 l3 = __float2bfloat16(v.w - __bfloat162float(h3));
    ((__nv_bfloat162*)hi)[2*i]   = __nv_bfloat162{h0, h1};
    ((__nv_bfloat162*)hi)[2*i+1] = __nv_bfloat162{h2, h3};
    ((__nv_bfloat162*)lo)[2*i]   = __nv_bfloat162{l0, l1};
    ((__nv_bfloat162*)lo)[2*i+1] = __nv_bfloat162{l2, l3};
}

// ---------------------------------------------------------------------------
// 4-key attention; writes attn directly as bf16 hi/lo split.
// ---------------------------------------------------------------------------
__global__ void __launch_bounds__(256)
attn_kernel(const float* __restrict__ h_prev, const float* __restrict__ xproj,
            const float* __restrict__ q,
            __nv_bfloat16* __restrict__ ahi, __nv_bfloat16* __restrict__ alo)
{
    const int gw   = (blockIdx.x * 256 + threadIdx.x) >> 5;
    const int lane = threadIdx.x & 31;
    if (gw >= B_ * NH_) return;
    const size_t base = (size_t)(gw / NH_) * H_ + (size_t)(gw % NH_) * HD_;

    const float4* qp = (const float4*)(q + base);
    const float4* hp = (const float4*)(h_prev + base);
    const float4* xp = (const float4*)(xproj + base);

    float s0 = 0.f, s1 = 0.f, s3 = 0.f;
    float4 hv[4], xv[4];
#pragma unroll
    for (int i = 0; i < 4; i++) {
        float4 q4 = qp[i * 32 + lane];
        float4 h4 = hp[i * 32 + lane];
        float4 x4 = xp[i * 32 + lane];
        hv[i] = h4; xv[i] = x4;
        s0 += q4.x * h4.x + q4.y * h4.y + q4.z * h4.z + q4.w * h4.w;
        s1 += q4.x * x4.x + q4.y * x4.y + q4.z * x4.z + q4.w * x4.w;
        s3 += q4.x * h4.x * x4.x + q4.y * h4.y * x4.y +
              q4.z * h4.z * x4.z + q4.w * h4.w * x4.w;
    }
#pragma unroll
    for (int off = 16; off > 0; off >>= 1) {
        s0 += __shfl_xor_sync(0xffffffffu, s0, off);
        s1 += __shfl_xor_sync(0xffffffffu, s1, off);
        s3 += __shfl_xor_sync(0xffffffffu, s3, off);
    }
    const float inv = rsqrtf((float)HD_);
    float sc0 = s0 * inv, sc1 = s1 * inv, sc2 = (s0 + s1) * inv, sc3 = s3 * inv;
    float m  = fmaxf(fmaxf(sc0, sc1), fmaxf(sc2, sc3));
    float e0 = expf(sc0 - m), e1 = expf(sc1 - m), e2 = expf(sc2 - m), e3 = expf(sc3 - m);
    float rs = 1.0f / (e0 + e1 + e2 + e3);
    float w0 = e0 * rs, w1 = e1 * rs, w2 = e2 * rs, w3 = e3 * rs;
    float ch = w0 + w2, cx = w1 + w2;

    __nv_bfloat162* ohp = (__nv_bfloat162*)(ahi + base);
    __nv_bfloat162* olp = (__nv_bfloat162*)(alo + base);
#pragma unroll
    for (int i = 0; i < 4; i++) {
        float4 h4 = hv[i], x4 = xv[i];
        float o0 = ch * h4.x + cx * x4.x + w3 * h4.x * x4.x;
        float o1 = ch * h4.y + cx * x4.y + w3 * h4.y * x4.y;
        float o2 = ch * h4.z + cx * x4.z + w3 * h4.z * x4.z;
        float o3 = ch * h4.w + cx * x4.w + w3 * h4.w * x4.w;
        __nv_bfloat16 h0 = __float2bfloat16(o0), h1 = __float2bfloat16(o1);
        __nv_bfloat16 h2 = __float2bfloat16(o2), h3 = __float2bfloat16(o3);
        __nv_bfloat16 l0 = __float2bfloat16(o0 - __bfloat162float(h0));
        __nv_bfloat16 l1 = __float2bfloat16(o1 - __bfloat162float(h1));
        __nv_bfloat16 l2 = __float2bfloat16(o2 - __bfloat162float(h2));
        __nv_bfloat16 l3 = __float2bfloat16(o3 - __bfloat162float(h3));
        int idx = (i * 32 + lane) * 2;
        ohp[idx]   = __nv_bfloat162{h0, h1};
        ohp[idx+1] = __nv_bfloat162{h2, h3};
        olp[idx]   = __nv_bfloat162{l0, l1};
        olp[idx+1] = __nv_bfloat162{l2, l3};
    }
}

// ---------------------------------------------------------------------------
// LayerNorm + gated mix
// ---------------------------------------------------------------------------
__global__ void __launch_bounds__(256)
ln_gate_kernel(const float* __restrict__ attn_g, const float* __restrict__ h_prev,
               const float* __restrict__ gate, const float* __restrict__ gamma,
               const float* __restrict__ beta, float* __restrict__ out)
{
    const int b   = blockIdx.x;
    const int tid = threadIdx.x;
    const size_t rb = (size_t)b * H_;

    float4 y[2], h4[2];
    float sum = 0.f, sq = 0.f;
#pragma unroll
    for (int c = 0; c < 2; c++) {
        int d = c * 1024 + tid * 4;
        float4 a  = *(const float4*)(attn_g + rb + d);
        float4 hh = *(const float4*)(h_prev + rb + d);
        float4 yy = make_float4(a.x + hh.x, a.y + hh.y, a.z + hh.z, a.w + hh.w);
        y[c] = yy; h4[c] = hh;
        sum += yy.x + yy.y + yy.z + yy.w;
        sq  += yy.x * yy.x + yy.y * yy.y + yy.z * yy.z + yy.w * yy.w;
    }
#pragma unroll
    for (int off = 16; off > 0; off >>= 1) {
        sum += __shfl_xor_sync(0xffffffffu, sum, off);
        sq  += __shfl_xor_sync(0xffffffffu, sq,  off);
    }
    __shared__ float s_sum[8], s_sq[8];
    __shared__ float s_mu, s_rstd;
    if ((tid & 31) == 0) { s_sum[tid >> 5] = sum; s_sq[tid >> 5] = sq; }
    __syncthreads();
    if (tid == 0) {
        float S = 0.f, Q = 0.f;
#pragma unroll
        for (int i = 0; i < 8; i++) { S += s_sum[i]; Q += s_sq[i]; }
        float mu  = S / (float)H_;
        float var = Q / (float)H_ - mu * mu;
        s_mu = mu;
        s_rstd = rsqrtf(var + EPS_);
    }
    __syncthreads();
    const float mu = s_mu, rstd = s_rstd;

#pragma unroll
    for (int c = 0; c < 2; c++) {
        int d = c * 1024 + tid * 4;
        float4 g4 = *(const float4*)(gate  + rb + d);
        float4 gm = *(const float4*)(gamma + d);
        float4 bt = *(const float4*)(beta  + d);
        float4 yy = y[c], hh = h4[c], o;
        float c0 = (yy.x - mu) * rstd * gm.x + bt.x;
        float c1 = (yy.y - mu) * rstd * gm.y + bt.y;
        float c2 = (yy.z - mu) * rstd * gm.z + bt.z;
        float c3 = (yy.w - mu) * rstd * gm.w + bt.w;
        o.x = g4.x * c0 + (1.0f - g4.x) * hh.x;
        o.y = g4.y * c1 + (1.0f - g4.y) * hh.y;
        o.z = g4.z * c2 + (1.0f - g4.z) * hh.z;
        o.w = g4.w * c3 + (1.0f - g4.w) * hh.w;
        *(float4*)(out + rb + d) = o;
    }
}

// ---------------------------------------------------------------------------
extern "C" void kernel_launch(void* const* d_in, const int* in_sizes, int n_in,
                              void* d_out, int out_size)
{
    const float* h_prev = (const float*)d_in[0];
    const float* x      = (const float*)d_in[1];
    const float* W_proj = (const float*)d_in[2];
    const float* b_proj = (const float*)d_in[3];
    const float* W_q    = (const float*)d_in[4];
    const float* b_q    = (const float*)d_in[5];
    const float* W_o    = (const float*)d_in[6];
    const float* b_o    = (const float*)d_in[7];
    const float* W_g    = (const float*)d_in[8];
    const float* b_g    = (const float*)d_in[9];
    const float* gamma  = (const float*)d_in[10];
    const float* beta   = (const float*)d_in[11];
    float* out = (float*)d_out;

    float *buf0, *buf1, *buf2;
    __nv_bfloat16 *xsh, *xsl, *hsh, *hsl, *ath, *atl, *agh, *agl;
    __nv_bfloat16 *wph, *wpl, *wqh, *wql, *woh, *wol, *wgh, *wgl;
    cudaGetSymbolAddress((void**)&buf0, g_buf0);
    cudaGetSymbolAddress((void**)&buf1, g_buf1);
    cudaGetSymbolAddress((void**)&buf2, g_buf2);
    cudaGetSymbolAddress((void**)&xsh, g_xs_hi);
    cudaGetSymbolAddress((void**)&xsl, g_xs_lo);
    cudaGetSymbolAddress((void**)&hsh, g_hs_hi);
    cudaGetSymbolAddress((void**)&hsl, g_hs_lo);
    cudaGetSymbolAddress((void**)&ath, g_at_hi);
    cudaGetSymbolAddress((void**)&atl, g_at_lo);
    cudaGetSymbolAddress((void**)&agh, g_ag_hi);
    cudaGetSymbolAddress((void**)&agl, g_ag_lo);
    cudaGetSymbolAddress((void**)&wph, g_wp_hi);
    cudaGetSymbolAddress((void**)&wpl, g_wp_lo);
    cudaGetSymbolAddress((void**)&wqh, g_wq_hi);
    cudaGetSymbolAddress((void**)&wql, g_wq_lo);
    cudaGetSymbolAddress((void**)&woh, g_wo_hi);
    cudaGetSymbolAddress((void**)&wol, g_wo_lo);
    cudaGetSymbolAddress((void**)&wgh, g_wg_hi);
    cudaGetSymbolAddress((void**)&wgl, g_wg_lo);

    cudaFuncSetAttribute(gemm_mma<0, false>, cudaFuncAttributeMaxDynamicSharedMemorySize, SMEM_BYTES);
    cudaFuncSetAttribute(gemm_mma<1, true >, cudaFuncAttributeMaxDynamicSharedMemorySize, SMEM_BYTES);
    cudaFuncSetAttribute(gemm_mma<2, false>, cudaFuncAttributeMaxDynamicSharedMemorySize, SMEM_BYTES);

    // splits of inputs/weights
    {
        int n4;
        n4 = B_ * IN_ / 4;     split_kernel<<<n4 / 256, 256>>>(x, xsh, xsl, n4);
        n4 = B_ * H_ / 4;      split_kernel<<<n4 / 256, 256>>>(h_prev, hsh, hsl, n4);
        n4 = H_ * IN_ / 4;     split_kernel<<<n4 / 256, 256>>>(W_proj, wph, wpl, n4);
        n4 = H_ * H_ / 4;      split_kernel<<<n4 / 256, 256>>>(W_q, wqh, wql, n4);
        n4 = H_ * H_ / 4;      split_kernel<<<n4 / 256, 256>>>(W_o, woh, wol, n4);
        n4 = H_ * 2 * H_ / 4;  split_kernel<<<n4 / 256, 256>>>(W_g, wgh, wgl, n4);
    }

    dim3 grid(H_ / 128, B_ / 128);   // (16, 64)

    // 1) x_proj = x @ W_proj^T + b_proj            -> buf0
    gemm_mma<0, false><<<grid, 256, SMEM_BYTES>>>(
        xsh, xsl, xsh, xsl, IN_, wph, wpl, b_proj, buf0, nullptr, nullptr,
        B_, H_, IN_);
    // 2) q = h_prev @ W_q^T + b_q                  -> buf1
    gemm_mma<0, false><<<grid, 256, SMEM_BYTES>>>(
        hsh, hsl, hsh, hsl, H_, wqh, wql, b_q, buf1, nullptr, nullptr,
        B_, H_, H_);
    // 3) attention -> attn split (bf16 hi/lo)
    attn_kernel<<<(B_ * NH_) / 8, 256>>>(h_prev, buf0, buf1, ath, atl);
    // 4) attn_gelu = gelu(attn @ W_o^T + b_o)      -> buf2 (fp32) + bf16 split
    gemm_mma<1, true><<<grid, 256, SMEM_BYTES>>>(
        ath, atl, ath, atl, H_, woh, wol, b_o, buf2, agh, agl,
        B_, H_, H_);
    // 5) gate = sigmoid([h_prev, attn_gelu] @ W_g^T + b_g) -> buf1
    gemm_mma<2, false><<<grid, 256, SMEM_BYTES>>>(
        hsh, hsl, agh, agl, H_, wgh, wgl, b_g, buf1, nullptr, nullptr,
        B_, H_, 2 * H_);
    // 6) layernorm + gated mix                     -> out
    ln_gate_kernel<<<B_, 256>>>(buf2, h_prev, buf1, gamma, beta, out);
}